// round 17
// baseline (speedup 1.0000x reference)
#include <cuda_runtime.h>
#include <cuda_fp16.h>
#include <cstdint>

#define TIN  20
#define TDEC 45
#define TTOT 65
#define NTH  256
#define ROWS 64

// prepped fp16 weights in mma FRAGMENT order.
// u32 units: mats {eL0@0(8ch), dL0@32768, eL1@65536(16ch), dL1@131072} (u32 idx)
// chunk (4096 u32 = 16KB): [wn 0..3][i 0..7][lane 0..31][v 0..3]
//   i = 2*j + khalf  (j = n8 block 0..3, khalf = k32 half of the k64 chunk)
__device__ __align__(256) __half g_wbuf[393216];
// prepped f32 tables: be0@0 be1@512 bd0@1024 bd1@1536 | wie0@2048 wie1@2560 wid0@3072 wid1@3584
__device__ __align__(256) float g_tbl[4096];

// smem layout (byte offsets):
// [0, 65536)  4 x 16KB A-state buffers: AB(reg,pp) = reg*32768 + pp*16384
//             reg0=h0, reg1=h1; 64 rows x 128 cols fp16 (256B/row), XOR-swizzled 16B units
#define OFF_TBL 65536      // staged: biasL0[512] biasL1[512] wx0[512] wx1[512]
#define OFF_FCW 73728      // 256 f32
#define OFF_FCB 74752      // 2 f32 (padded)
#define OFF_XD  74768      // 64 x 2 f32
#define SMEM_TOTAL 75392

#define AB(reg, pp) ((uint32_t)((reg) * 32768 + (pp) * 16384))

__device__ __forceinline__ uint32_t smem_u32(const void* p) {
    uint32_t a;
    asm("{ .reg .u64 t; cvta.to.shared.u64 t, %1; cvt.u32.u64 %0, t; }" : "=r"(a) : "l"(p));
    return a;
}
__device__ __forceinline__ void ldsm4(uint32_t* r, uint32_t a) {
    asm volatile("ldmatrix.sync.aligned.m8n8.x4.shared.b16 {%0,%1,%2,%3}, [%4];"
                 : "=r"(r[0]), "=r"(r[1]), "=r"(r[2]), "=r"(r[3]) : "r"(a));
}
__device__ __forceinline__ void mma16816(float* d, const uint32_t* a, uint32_t b0, uint32_t b1) {
    asm volatile("mma.sync.aligned.m16n8k16.row.col.f32.f16.f16.f32 "
                 "{%0,%1,%2,%3}, {%4,%5,%6,%7}, {%8,%9}, {%0,%1,%2,%3};"
                 : "+f"(d[0]), "+f"(d[1]), "+f"(d[2]), "+f"(d[3])
                 : "r"(a[0]), "r"(a[1]), "r"(a[2]), "r"(a[3]), "r"(b0), "r"(b1));
}
__device__ __forceinline__ float sigf(float x)   { return __fdividef(1.0f, 1.0f + __expf(-x)); }
__device__ __forceinline__ float tanhf_(float x) { return 2.0f * __fdividef(1.0f, 1.0f + __expf(-2.0f * x)) - 1.0f; }
__device__ __forceinline__ float h2lo(uint32_t w) {
    return __half2float(__ushort_as_half((unsigned short)(w & 0xffffu)));
}
__device__ __forceinline__ float h2hi(uint32_t w) {
    return __half2float(__ushort_as_half((unsigned short)(w >> 16)));
}

// ---------------- prep: weights -> fragment-ordered fp16 (unchanged from R16) ----------------
__global__ __launch_bounds__(256)
void prep_weights(const float* __restrict__ eWhh0, const float* __restrict__ dWhh0,
                  const float* __restrict__ eWih1, const float* __restrict__ eWhh1,
                  const float* __restrict__ dWih1, const float* __restrict__ dWhh1)
{
    int e = blockIdx.x * 256 + threadIdx.x;       // u32 index
    if (e >= 196608) return;
    int mat, base, NCK;
    if      (e < 32768)  { mat = 0; base = 0;      NCK = 2; }
    else if (e < 65536)  { mat = 1; base = 32768;  NCK = 2; }
    else if (e < 131072) { mat = 2; base = 65536;  NCK = 4; }
    else                 { mat = 3; base = 131072; NCK = 4; }
    int loc = e - base;
    int ci = loc >> 12, w = loc & 4095;
    int wn = w >> 10, r = w & 1023;
    int i = r >> 7, l = (r >> 2) & 31, v = r & 3;
    int j = i >> 1, khalf = i & 1;
    int k8 = 4 * khalf + v;
    int np = 32 * wn + 8 * j + (l >> 2);
    int kc = 8 * k8 + 2 * (l & 3);
    int p = ci / NCK, ck = ci % NCK;
    int col = 128 * p + np;
    int orig = (col & 3) * 128 + (col >> 2);      // gate g*128 + j
    int kg = 64 * ck + kc;

    float w0, w1;
    if (mat == 0)      { w0 = eWhh0[orig * 128 + kg]; w1 = eWhh0[orig * 128 + kg + 1]; }
    else if (mat == 1) { w0 = dWhh0[orig * 128 + kg]; w1 = dWhh0[orig * 128 + kg + 1]; }
    else {
        const float* Wi = (mat == 2) ? eWih1 : dWih1;
        const float* Wh = (mat == 2) ? eWhh1 : dWhh1;
        w0 = (kg < 128)     ? Wi[orig * 128 + kg]       : Wh[orig * 128 + (kg - 128)];
        w1 = (kg + 1 < 128) ? Wi[orig * 128 + kg + 1]   : Wh[orig * 128 + (kg + 1 - 128)];
    }
    const uint32_t pk = (uint32_t)__half_as_ushort(__float2half_rn(w0)) |
                        ((uint32_t)__half_as_ushort(__float2half_rn(w1)) << 16);
    ((uint32_t*)g_wbuf)[e] = pk;
}

__global__ __launch_bounds__(256)
void prep_tables(const float* __restrict__ ebih0, const float* __restrict__ ebhh0,
                 const float* __restrict__ ebih1, const float* __restrict__ ebhh1,
                 const float* __restrict__ dbih0, const float* __restrict__ dbhh0,
                 const float* __restrict__ dbih1, const float* __restrict__ dbhh1,
                 const float* __restrict__ eWih0, const float* __restrict__ dWih0)
{
    int i = blockIdx.x * 256 + threadIdx.x;
    if (i >= 4096) return;
    int col = i & 511;
    int orig = (col & 3) * 128 + (col >> 2);
    int seg = i >> 9;
    float v;
    switch (seg) {
        case 0: v = ebih0[orig] + ebhh0[orig]; break;
        case 1: v = ebih1[orig] + ebhh1[orig]; break;
        case 2: v = dbih0[orig] + dbhh0[orig]; break;
        case 3: v = dbih1[orig] + dbhh1[orig]; break;
        case 4: v = eWih0[2 * orig];     break;
        case 5: v = eWih0[2 * orig + 1]; break;
        case 6: v = dWih0[2 * orig];     break;
        default: v = dWih0[2 * orig + 1]; break;
    }
    g_tbl[i] = v;
}

// ---------------- one layer: B via LDG fragments, A via ldsm, no inner barriers ----------------
// mrow: warp's row base (32*wm). Warp tile m32n32; 2 m-group warps share B lines via L1.
template <int K>
__device__ __forceinline__ void gemm_layer(
    char* sm, uint32_t sA, const uint4* __restrict__ wmat,
    const float* __restrict__ bias, const float* __restrict__ wx0,
    const float* __restrict__ wx1, bool use_x,
    const float* xs0, const float* xs1,
    float* cst, int lane, int wn, int mrow,
    uint32_t aB0, uint32_t aB1, uint32_t wT)
{
    constexpr int NCK = K / 64;          // k64-chunks per pass
    constexpr int NCT = 4 * NCK;         // total chunks
    constexpr int H = 2 * NCT;           // k32 halves
    const int l8 = lane & 7;
    const int lkh = (lane >> 4) & 1;
    const uint4* wl = wmat + wn * 256 + lane;

    uint4 cur[4], nxt[4];
    auto ldB = [&](uint4 q[4], int h) {
        const uint4* bp = wl + (size_t)(h >> 1) * 1024 + (h & 1) * 32;
        q[0] = __ldg(bp);
        q[1] = __ldg(bp + 64);
        q[2] = __ldg(bp + 128);
        q[3] = __ldg(bp + 192);
    };
    ldB(cur, 0);
    ldB(nxt, 1);

    #pragma unroll
    for (int p = 0; p < 4; p++) {
        // accumulator init: bias (+ x-term for layer 0)
        float acc[2][4][4];
        #pragma unroll
        for (int nt = 0; nt < 4; nt++) {
            const int col0 = 128 * p + 32 * wn + 8 * nt + 2 * (lane & 3);
            const float b0 = bias[col0], b1 = bias[col0 + 1];
            #pragma unroll
            for (int mi = 0; mi < 2; mi++) {
                if (use_x) {
                    const float w00 = wx0[col0], w01 = wx0[col0 + 1];
                    const float w10 = wx1[col0], w11 = wx1[col0 + 1];
                    acc[mi][nt][0] = fmaf(w10, xs1[2 * mi],     fmaf(w00, xs0[2 * mi],     b0));
                    acc[mi][nt][1] = fmaf(w11, xs1[2 * mi],     fmaf(w01, xs0[2 * mi],     b1));
                    acc[mi][nt][2] = fmaf(w10, xs1[2 * mi + 1], fmaf(w00, xs0[2 * mi + 1], b0));
                    acc[mi][nt][3] = fmaf(w11, xs1[2 * mi + 1], fmaf(w01, xs0[2 * mi + 1], b1));
                } else {
                    acc[mi][nt][0] = b0; acc[mi][nt][1] = b1;
                    acc[mi][nt][2] = b0; acc[mi][nt][3] = b1;
                }
            }
        }

        #pragma unroll
        for (int ck = 0; ck < NCK; ck++) {
            const int h0 = (p * NCK + ck) * 2;
            const uint32_t aB = (K == 256 && ck >= NCK / 2) ? aB1 : aB0;
            const uint32_t arA = sA + aB + (uint32_t)(mrow + (lane & 15)) * 256u;
            // ---- half 0 (cur): ks = 0,1 ----
            #pragma unroll
            for (int s = 0; s < 2; s++) {
                const uint32_t cu =
                    ((uint32_t)((8 * ck + 2 * s + lkh) & 15)) ^ (uint32_t)l8;
                uint32_t a0[4], a1[4];
                ldsm4(a0, arA + (cu << 4));
                ldsm4(a1, arA + 4096u + (cu << 4));
                #pragma unroll
                for (int j = 0; j < 4; j++) {
                    const uint32_t b0 = s ? cur[j].z : cur[j].x;
                    const uint32_t b1 = s ? cur[j].w : cur[j].y;
                    mma16816(acc[0][j], a0, b0, b1);
                    mma16816(acc[1][j], a1, b0, b1);
                }
            }
            if (h0 + 2 < H) ldB(cur, h0 + 2);
            // ---- half 1 (nxt): ks = 2,3 ----
            #pragma unroll
            for (int s = 0; s < 2; s++) {
                const uint32_t cu =
                    ((uint32_t)((8 * ck + 4 + 2 * s + lkh) & 15)) ^ (uint32_t)l8;
                uint32_t a0[4], a1[4];
                ldsm4(a0, arA + (cu << 4));
                ldsm4(a1, arA + 4096u + (cu << 4));
                #pragma unroll
                for (int j = 0; j < 4; j++) {
                    const uint32_t b0 = s ? nxt[j].z : nxt[j].x;
                    const uint32_t b1 = s ? nxt[j].w : nxt[j].y;
                    mma16816(acc[0][j], a0, b0, b1);
                    mma16816(acc[1][j], a1, b0, b1);
                }
            }
            if (h0 + 3 < H) ldB(nxt, h0 + 3);
        }

        // epilogue pass p: gates -> (c,h); write h (fp16) to pong buffer
        const int odd = lane & 1;
        #pragma unroll
        for (int mi = 0; mi < 2; mi++) {
            const int rowE = mrow + 16 * mi + (lane >> 2) + (odd ? 8 : 0);
            uint32_t hp4[4];
            #pragma unroll
            for (int nt = 0; nt < 4; nt++) {
                const float e0 = __shfl_xor_sync(0xffffffffu, acc[mi][nt][0], 1);
                const float e1 = __shfl_xor_sync(0xffffffffu, acc[mi][nt][1], 1);
                const float e2 = __shfl_xor_sync(0xffffffffu, acc[mi][nt][2], 1);
                const float e3 = __shfl_xor_sync(0xffffffffu, acc[mi][nt][3], 1);
                float xi, xf, xg, xo;
                if (!odd) { xi = acc[mi][nt][0]; xf = acc[mi][nt][1]; xg = e0; xo = e1; }
                else      { xi = e2; xf = e3; xg = acc[mi][nt][2]; xo = acc[mi][nt][3]; }
                const int cidx = (2 * p + mi) * 4 + nt;
                const float cn = fmaf(sigf(xf), cst[cidx], sigf(xi) * tanhf_(xg));
                cst[cidx] = cn;
                const float h = sigf(xo) * tanhf_(cn);
                const uint32_t v = (uint32_t)__half_as_ushort(__float2half_rn(h));
                const uint32_t vx = __shfl_xor_sync(0xffffffffu, v, 2);
                hp4[nt] = v | (vx << 16);
            }
            if ((lane & 2) == 0) {
                const uint32_t cuw = ((uint32_t)(4 * p + wn)) ^ (uint32_t)(rowE & 7);
                *(uint4*)(sm + wT + rowE * 256 + (cuw << 4)) =
                    make_uint4(hp4[0], hp4[1], hp4[2], hp4[3]);
            }
        }
    }
}

// ---------------- main kernel ----------------
__global__ void __launch_bounds__(NTH, 2)
lstm_mma_kernel(const float* __restrict__ inseq,
                const float* __restrict__ fcW, const float* __restrict__ fcbp,
                float* __restrict__ out)
{
    extern __shared__ char sm[];
    const uint32_t sA = smem_u32(sm);
    float* tbl  = (float*)(sm + OFF_TBL);
    float* fcw  = (float*)(sm + OFF_FCW);
    float* fcb  = (float*)(sm + OFF_FCB);
    float* xdec = (float*)(sm + OFF_XD);

    const int tid = threadIdx.x;
    const int lane = tid & 31;
    const int wn = (tid >> 5) & 3;              // n-group 0..3
    const int wm = tid >> 7;                    // m-group 0..1
    const int mrow = 32 * wm;
    const int bm = blockIdx.x * ROWS;
    const int ra = lane >> 2;

    for (int i = tid; i < 256; i += NTH) fcw[i] = fcW[i];
    if (tid < 2) fcb[tid] = fcbp[tid];
    if (tid < 2 * ROWS)
        xdec[tid] = inseq[(size_t)(bm + (tid >> 1)) * 40 + 38 + (tid & 1)];
    for (int i = tid; i < 16384; i += NTH)      // zero all 4 A buffers (64KB)
        ((uint32_t*)sm)[i] = 0u;
    __syncthreads();

    float c0[32], c1[32];
    #pragma unroll
    for (int i = 0; i < 32; i++) { c0[i] = 0.0f; c1[i] = 0.0f; }

    int cur0 = 0, cur1 = 0;
    const int r4[4] = { mrow + ra, mrow + ra + 8, mrow + ra + 16, mrow + ra + 24 };

    for (int t = 0; t < TTOT; t++) {
        const bool enc = t < TIN;
        if (t == 0 || t == TIN) {
            for (int i = tid; i < 2048; i += NTH) {
                const int seg = i >> 9, idx = i & 511;
                int srcoff;
                if      (seg == 0) srcoff = (enc ? 0 : 1024) + idx;
                else if (seg == 1) srcoff = (enc ? 512 : 1536) + idx;
                else if (seg == 2) srcoff = 2048 + (enc ? 0 : 1024) + idx;
                else               srcoff = 2560 + (enc ? 0 : 1024) + idx;
                tbl[i] = g_tbl[srcoff];
            }
            __syncthreads();
        }
        float xs0[4], xs1[4];
        #pragma unroll
        for (int g = 0; g < 4; g++) {
            if (enc) {
                const float2 xv =
                    *(const float2*)(inseq + (size_t)(bm + r4[g]) * 40 + 2 * t);
                xs0[g] = xv.x; xs1[g] = xv.y;
            } else {
                xs0[g] = xdec[r4[g] * 2];
                xs1[g] = xdec[r4[g] * 2 + 1];
            }
        }
        // ---- layer 0: reads h0[cur0], writes h0[cur0^1] ----
        gemm_layer<128>(sm, sA, (const uint4*)g_wbuf + (enc ? 0 : 8192),
                        tbl, tbl + 1024, tbl + 1536, true, xs0, xs1,
                        c0, lane, wn, mrow,
                        AB(0, cur0), AB(0, cur0), AB(0, cur0 ^ 1));
        cur0 ^= 1;
        __syncthreads();   // h0-new visible for L1
        // ---- layer 1: reads [h0 new | h1 old], writes h1[cur1^1] ----
        gemm_layer<256>(sm, sA, (const uint4*)g_wbuf + (enc ? 16384 : 32768),
                        tbl + 512, nullptr, nullptr, false, xs0, xs1,
                        c1, lane, wn, mrow,
                        AB(0, cur0), AB(1, cur1), AB(1, cur1 ^ 1));
        cur1 ^= 1;
        __syncthreads();   // h1-new visible
        if (!enc) {
            if (tid < 2 * ROWS) {
                const int r = tid >> 1, o = tid & 1;
                const char* hB = sm + AB(1, cur1) + r * 256;
                float a = fcb[o];
                #pragma unroll 4
                for (int cu = 0; cu < 16; cu++) {
                    const uint32_t dc = ((uint32_t)cu) ^ (uint32_t)(r & 7);
                    const uint4 hq = *(const uint4*)(hB + (dc << 4));
                    const uint32_t hv[4] = {hq.x, hq.y, hq.z, hq.w};
                    #pragma unroll
                    for (int g = 0; g < 4; g++) {
                        a = fmaf(h2lo(hv[g]), fcw[o * 128 + 8 * cu + 2 * g], a);
                        a = fmaf(h2hi(hv[g]), fcw[o * 128 + 8 * cu + 2 * g + 1], a);
                    }
                }
                out[(size_t)(bm + r) * (TDEC * 2) + (t - TIN) * 2 + o] = a;
                xdec[tid] = a;
            }
            __syncthreads();   // xdec visible for next step
        }
    }
}

extern "C" void kernel_launch(void* const* d_in, const int* in_sizes, int n_in,
                              void* d_out, int out_size)
{
    (void)in_sizes; (void)n_in; (void)out_size;
    const float* inseq = (const float*)d_in[0];
    const float* eWih0 = (const float*)d_in[1];
    const float* eWhh0 = (const float*)d_in[2];
    const float* ebih0 = (const float*)d_in[3];
    const float* ebhh0 = (const float*)d_in[4];
    const float* eWih1 = (const float*)d_in[5];
    const float* eWhh1 = (const float*)d_in[6];
    const float* ebih1 = (const float*)d_in[7];
    const float* ebhh1 = (const float*)d_in[8];
    const float* dWih0 = (const float*)d_in[9];
    const float* dWhh0 = (const float*)d_in[10];
    const float* dbih0 = (const float*)d_in[11];
    const float* dbhh0 = (const float*)d_in[12];
    const float* dWih1 = (const float*)d_in[13];
    const float* dWhh1 = (const float*)d_in[14];
    const float* dbih1 = (const float*)d_in[15];
    const float* dbhh1 = (const float*)d_in[16];
    const float* fcW   = (const float*)d_in[17];
    const float* fcb   = (const float*)d_in[18];
    float* out = (float*)d_out;

    prep_weights<<<768, 256>>>(eWhh0, dWhh0, eWih1, eWhh1, dWih1, dWhh1);
    prep_tables<<<16, 256>>>(ebih0, ebhh0, ebih1, ebhh1,
                             dbih0, dbhh0, dbih1, dbhh1, eWih0, dWih0);

    cudaFuncSetAttribute(lstm_mma_kernel,
                         cudaFuncAttributeMaxDynamicSharedMemorySize, SMEM_TOTAL);
    lstm_mma_kernel<<<32768 / ROWS, NTH, SMEM_TOTAL>>>(inseq, fcW, fcb, out);
}